// round 4
// baseline (speedup 1.0000x reference)
#include <cuda_runtime.h>
#include <cstdint>

// B=256 batches of N=512 x 512 binary (0/1) float32 adjacency.
constexpr int B   = 256;
constexpr int N   = 512;
constexpr int W   = N / 32;    // 16 packed words per row
constexpr int WS  = W + 1;     // stride 17 (odd -> conflict-free column reads)
constexpr int F4  = N / 4;     // 128 float4 per row
constexpr int RPC = 64;        // rows per CTA
constexpr int CPB = N / RPC;   // 8 CTAs per batch -> grid 2048

__device__ int   g_flags[B];        // producers-done count per batch
__device__ float g_dis[(size_t)B * N];

__global__ void reset_kernel() { g_flags[threadIdx.x] = 0; }

// 2048 CTAs x 1024 threads. CTA (batch, chunk) owns rows [chunk*64, chunk*64+64).
__global__ void __launch_bounds__(1024)
fused_normalize_kernel(const float* __restrict__ adj, float* __restrict__ out) {
    __shared__ unsigned s_bits[RPC * WS];  // 4.4 KB packed rows (this chunk)
    __shared__ float    s_dis[N];          // full-batch d^-1/2

    const int batch = blockIdx.x >> 3;
    const int chunk = blockIdx.x & 7;
    const int r0    = chunk * RPC;

    const int tid  = threadIdx.x;
    const int wid  = tid >> 5;     // 0..31, each warp owns 2 local rows
    const int lane = tid & 31;
    const int sub  = lane & 7;
    const int grp  = lane >> 3;

    const float4* a4 = reinterpret_cast<const float4*>(adj)
                     + ((size_t)batch * N + r0) * F4;

    // ---- Phase A: pack 2 rows per warp; all 8 LDG.128 independent ----
    {
        const int lr0 = wid * 2;
        const int lr1 = lr0 + 1;
        const float4* p0 = a4 + (size_t)lr0 * F4;
        const float4* p1 = a4 + (size_t)lr1 * F4;

        float4 a[4], b[4];
        #pragma unroll
        for (int c = 0; c < 4; c++) {
            a[c] = __ldcs(&p0[c * 32 + lane]);
            b[c] = __ldcs(&p1[c * 32 + lane]);
        }
        #pragma unroll
        for (int c = 0; c < 4; c++) {
            unsigned n0 = (a[c].x != 0.0f ? 1u : 0u) | (a[c].y != 0.0f ? 2u : 0u) |
                          (a[c].z != 0.0f ? 4u : 0u) | (a[c].w != 0.0f ? 8u : 0u);
            unsigned n1 = (b[c].x != 0.0f ? 1u : 0u) | (b[c].y != 0.0f ? 2u : 0u) |
                          (b[c].z != 0.0f ? 4u : 0u) | (b[c].w != 0.0f ? 8u : 0u);
            unsigned w0 = n0 << (sub * 4);
            unsigned w1 = n1 << (sub * 4);
            w0 |= __shfl_xor_sync(0xffffffffu, w0, 1);
            w1 |= __shfl_xor_sync(0xffffffffu, w1, 1);
            w0 |= __shfl_xor_sync(0xffffffffu, w0, 2);
            w1 |= __shfl_xor_sync(0xffffffffu, w1, 2);
            w0 |= __shfl_xor_sync(0xffffffffu, w0, 4);
            w1 |= __shfl_xor_sync(0xffffffffu, w1, 4);
            if (sub == 0) {
                s_bits[lr0 * WS + c * 4 + grp] = w0;
                s_bits[lr1 * WS + c * 4 + grp] = w1;
            }
        }
    }
    __syncthreads();

    // ---- Degrees + diagonal patch for own 64 rows; publish dis chunk ----
    if (tid < RPC) {
        const int ig = r0 + tid;              // row index within batch
        unsigned w[W];
        int cnt = 0;
        #pragma unroll
        for (int t = 0; t < W; t++) {
            w[t] = s_bits[tid * WS + t];
            cnt += __popc(w[t]);
        }
        const int dw = ig >> 5, db = ig & 31;
        const int diag = (w[dw] >> db) & 1;
        const int mask = (cnt != 0) ? 1 : 0;          // atom_mask
        const int deg  = cnt - diag + mask;           // degree_hat
        if (diag != mask) s_bits[tid * WS + dw] = w[dw] ^ (1u << db);
        g_dis[(size_t)batch * N + ig] = (deg > 0) ? rsqrtf((float)deg) : 0.0f;
    }
    __syncthreads();

    // ---- Exchange: release our chunk, wait for all 8 chunks of this batch ----
    if (tid == 0) {
        __threadfence();                              // dis stores visible gpu-wide
        atomicAdd(&g_flags[batch], 1);
        volatile int* vf = &g_flags[batch];
        while (*vf != CPB) __nanosleep(64);
    }
    __syncthreads();

    // ---- Pull the full dis vector (2 KB, L2-hot) into smem ----
    if (tid < N / 4) {
        reinterpret_cast<float4*>(s_dis)[tid] =
            __ldcg(reinterpret_cast<const float4*>(g_dis + (size_t)batch * N) + tid);
    }
    __syncthreads();

    // ---- Phase B: out[i][j] = dis[i]*dis[j]*bit(i,j); 2 rows/warp, STG.128 ----
    const float4* d4 = reinterpret_cast<const float4*>(s_dis);
    float4 dreg[4];
    #pragma unroll
    for (int c = 0; c < 4; c++) dreg[c] = d4[c * 32 + lane];  // row-invariant

    float4* o4 = reinterpret_cast<float4*>(out) + ((size_t)batch * N + r0) * F4;
    {
        const int lr0 = wid * 2;
        const int lr1 = lr0 + 1;
        const float di0 = s_dis[r0 + lr0];
        const float di1 = s_dis[r0 + lr1];
        float4* q0 = o4 + (size_t)lr0 * F4;
        float4* q1 = o4 + (size_t)lr1 * F4;

        #pragma unroll
        for (int c = 0; c < 4; c++) {
            const unsigned w0 = s_bits[lr0 * WS + c * 4 + grp];  // 8-lane broadcast
            const unsigned w1 = s_bits[lr1 * WS + c * 4 + grp];
            const unsigned n0 = (w0 >> (sub * 4)) & 0xFu;
            const unsigned n1 = (w1 >> (sub * 4)) & 0xFu;
            const float4 d = dreg[c];
            float4 v0, v1;
            v0.x = (n0 & 1u) ? di0 * d.x : 0.0f;
            v0.y = (n0 & 2u) ? di0 * d.y : 0.0f;
            v0.z = (n0 & 4u) ? di0 * d.z : 0.0f;
            v0.w = (n0 & 8u) ? di0 * d.w : 0.0f;
            v1.x = (n1 & 1u) ? di1 * d.x : 0.0f;
            v1.y = (n1 & 2u) ? di1 * d.y : 0.0f;
            v1.z = (n1 & 4u) ? di1 * d.z : 0.0f;
            v1.w = (n1 & 8u) ? di1 * d.w : 0.0f;
            __stcs(&q0[c * 32 + lane], v0);
            __stcs(&q1[c * 32 + lane], v1);
        }
    }
}

extern "C" void kernel_launch(void* const* d_in, const int* in_sizes, int n_in,
                              void* d_out, int out_size) {
    const float* adj = (const float*)d_in[0];
    float* out = (float*)d_out;
    (void)in_sizes; (void)n_in; (void)out_size;

    reset_kernel<<<1, B>>>();
    fused_normalize_kernel<<<B * CPB, 1024>>>(adj, out);
}

// round 5
// speedup vs baseline: 1.5138x; 1.5138x over previous
#include <cuda_runtime.h>
#include <cooperative_groups.h>
#include <cstdint>

namespace cg = cooperative_groups;

// B=256 batches of N=512 x 512 binary (0/1) float32 adjacency.
constexpr int B   = 256;
constexpr int N   = 512;
constexpr int W   = N / 32;    // 16 packed words per row
constexpr int WS  = W + 1;     // stride 17 (odd -> conflict-free column reads)
constexpr int F4  = N / 4;     // 128 float4 per row
constexpr int CPB = 4;         // CTAs (cluster size) per batch
constexpr int RPC = N / CPB;   // 128 rows per CTA

__device__ float g_dis[(size_t)B * N];   // d^-1/2 exchange (L2-hot, 512 KB)

// 1024 CTAs x 256 threads; cluster of 4 = one batch. 6 CTAs/SM.
__global__ void __launch_bounds__(256, 6) __cluster_dims__(CPB, 1, 1)
fused_normalize_kernel(const float* __restrict__ adj, float* __restrict__ out) {
    __shared__ unsigned s_bits[RPC * WS];  // 8.7 KB packed rows (this quarter)
    __shared__ float    s_dis[N];          // full-batch d^-1/2 (2 KB)

    cg::cluster_group cluster = cg::this_cluster();

    const int batch = blockIdx.x >> 2;   // cluster id
    const int rank  = blockIdx.x & 3;    // CTA rank within cluster
    const int r0    = rank * RPC;        // first row owned by this CTA

    const int tid  = threadIdx.x;
    const int wid  = tid >> 5;           // 0..7, each warp packs 16 rows
    const int lane = tid & 31;
    const int sub  = lane & 7;
    const int grp  = lane >> 3;

    const float4* a4 = reinterpret_cast<const float4*>(adj)
                     + ((size_t)batch * N + r0) * F4;

    // ---- Phase A: pack 2 rows per iteration (8 independent LDG.128) ----
    #pragma unroll 1
    for (int k = 0; k < 8; k++) {
        const int lr0 = wid * 16 + 2 * k;
        const int lr1 = lr0 + 1;
        const float4* p0 = a4 + (size_t)lr0 * F4;
        const float4* p1 = a4 + (size_t)lr1 * F4;

        float4 a[4], b[4];
        #pragma unroll
        for (int c = 0; c < 4; c++) {
            a[c] = __ldcs(&p0[c * 32 + lane]);
            b[c] = __ldcs(&p1[c * 32 + lane]);
        }
        #pragma unroll
        for (int c = 0; c < 4; c++) {
            unsigned n0 = (a[c].x != 0.0f ? 1u : 0u) | (a[c].y != 0.0f ? 2u : 0u) |
                          (a[c].z != 0.0f ? 4u : 0u) | (a[c].w != 0.0f ? 8u : 0u);
            unsigned n1 = (b[c].x != 0.0f ? 1u : 0u) | (b[c].y != 0.0f ? 2u : 0u) |
                          (b[c].z != 0.0f ? 4u : 0u) | (b[c].w != 0.0f ? 8u : 0u);
            unsigned w0 = n0 << (sub * 4);
            unsigned w1 = n1 << (sub * 4);
            w0 |= __shfl_xor_sync(0xffffffffu, w0, 1);
            w1 |= __shfl_xor_sync(0xffffffffu, w1, 1);
            w0 |= __shfl_xor_sync(0xffffffffu, w0, 2);
            w1 |= __shfl_xor_sync(0xffffffffu, w1, 2);
            w0 |= __shfl_xor_sync(0xffffffffu, w0, 4);
            w1 |= __shfl_xor_sync(0xffffffffu, w1, 4);
            if (sub == 0) {
                s_bits[lr0 * WS + c * 4 + grp] = w0;
                s_bits[lr1 * WS + c * 4 + grp] = w1;
            }
        }
    }
    __syncthreads();

    // ---- Patch own 128 rows: popc degrees, fix diagonal, publish dis ----
    if (tid < RPC) {
        const int ig = r0 + tid;                 // row index within batch
        unsigned w[W];
        int cnt = 0;
        #pragma unroll
        for (int t = 0; t < W; t++) {
            w[t] = s_bits[tid * WS + t];
            cnt += __popc(w[t]);
        }
        const int dw = ig >> 5, db = ig & 31;
        const int diag = (w[dw] >> db) & 1;
        const int mask = (cnt != 0) ? 1 : 0;     // atom_mask
        const int deg  = cnt - diag + mask;      // degree_hat
        if (diag != mask) s_bits[tid * WS + dw] = w[dw] ^ (1u << db);
        const float dis = (deg > 0) ? rsqrtf((float)deg) : 0.0f;
        g_dis[(size_t)batch * N + ig] = dis;     // publish (cluster.sync releases)
    }

    // ---- Exchange: HW-co-scheduled barrier, then pull full dis from L2 ----
    cluster.sync();
    if (tid < N / 4) {
        reinterpret_cast<float4*>(s_dis)[tid] =
            __ldcg(reinterpret_cast<const float4*>(g_dis + (size_t)batch * N) + tid);
    }
    __syncthreads();

    // ---- Phase B: out[i][j] = dis[i]*dis[j]*bit(i,j); 2 rows/iter, STG.128 ----
    const float4* d4 = reinterpret_cast<const float4*>(s_dis);
    float4 dreg[4];
    #pragma unroll
    for (int c = 0; c < 4; c++) dreg[c] = d4[c * 32 + lane];  // row-invariant

    float4* o4 = reinterpret_cast<float4*>(out) + ((size_t)batch * N + r0) * F4;

    #pragma unroll 1
    for (int k = 0; k < 8; k++) {
        const int lr0 = wid * 16 + 2 * k;
        const int lr1 = lr0 + 1;
        const float di0 = s_dis[r0 + lr0];
        const float di1 = s_dis[r0 + lr1];
        float4* q0 = o4 + (size_t)lr0 * F4;
        float4* q1 = o4 + (size_t)lr1 * F4;

        #pragma unroll
        for (int c = 0; c < 4; c++) {
            const unsigned w0 = s_bits[lr0 * WS + c * 4 + grp];  // 8-lane broadcast
            const unsigned w1 = s_bits[lr1 * WS + c * 4 + grp];
            const unsigned n0 = (w0 >> (sub * 4)) & 0xFu;
            const unsigned n1 = (w1 >> (sub * 4)) & 0xFu;
            const float4 d = dreg[c];
            float4 v0, v1;
            v0.x = (n0 & 1u) ? di0 * d.x : 0.0f;
            v0.y = (n0 & 2u) ? di0 * d.y : 0.0f;
            v0.z = (n0 & 4u) ? di0 * d.z : 0.0f;
            v0.w = (n0 & 8u) ? di0 * d.w : 0.0f;
            v1.x = (n1 & 1u) ? di1 * d.x : 0.0f;
            v1.y = (n1 & 2u) ? di1 * d.y : 0.0f;
            v1.z = (n1 & 4u) ? di1 * d.z : 0.0f;
            v1.w = (n1 & 8u) ? di1 * d.w : 0.0f;
            __stcs(&q0[c * 32 + lane], v0);
            __stcs(&q1[c * 32 + lane], v1);
        }
    }
}

extern "C" void kernel_launch(void* const* d_in, const int* in_sizes, int n_in,
                              void* d_out, int out_size) {
    const float* adj = (const float*)d_in[0];
    float* out = (float*)d_out;
    (void)in_sizes; (void)n_in; (void)out_size;

    fused_normalize_kernel<<<B * CPB, 256>>>(adj, out);
}

// round 6
// speedup vs baseline: 1.6972x; 1.1212x over previous
#include <cuda_runtime.h>
#include <cstdint>

// B=256 batches of N=512 x 512 binary (0/1) float32 adjacency.
constexpr int B       = 256;
constexpr int N       = 512;
constexpr int W       = N / 32;      // 16 packed words per row
constexpr int WS      = W + 1;       // stride 17 -> conflict-free column reads
constexpr int F4      = N / 4;       // 128 float4 per row
constexpr int RPC     = 32;          // rows per chunk (ticket)
constexpr int CHUNKS  = N / RPC;     // 16 chunks per batch
constexpr int TICKETS = B * CHUNKS;  // 4096
constexpr int GRID    = 592;         // 4 CTAs/SM * 148 SMs, all resident
constexpr int THREADS = 256;         // 8 warps; each warp owns 4 rows per ticket

__device__ float g_dis[(size_t)B * N];  // d^-1/2 exchange (512 KB, L2-hot)
__device__ int   g_done[B];             // completed A-chunks per batch
__device__ int   g_next;                // global ticket counter

__global__ void reset_kernel() {
    if (threadIdx.x < B) g_done[threadIdx.x] = 0;
    if (threadIdx.x == 0) g_next = 0;
}

__global__ void __launch_bounds__(THREADS, 4)
fused_normalize_kernel(const float* __restrict__ adj, float* __restrict__ out) {
    __shared__ unsigned s_bits[RPC * WS];  // 2.2 KB packed rows (this chunk)
    __shared__ float    s_dis[N];          // 2 KB full-batch d^-1/2
    __shared__ int      s_ticket;

    const int tid  = threadIdx.x;
    const int wid  = tid >> 5;   // 0..7
    const int lane = tid & 31;
    const int sub  = lane & 7;
    const int grp  = lane >> 3;

    for (;;) {
        if (tid == 0) s_ticket = atomicAdd(&g_next, 1);
        __syncthreads();
        const int t = s_ticket;
        if (t >= TICKETS) break;

        const int batch = t >> 4;          // t / CHUNKS
        const int chunk = t & 15;
        const int r0    = chunk * RPC;

        const float4* a4 = reinterpret_cast<const float4*>(adj)
                         + ((size_t)batch * N + r0) * F4;

        // ---- Phase A: pack 2 rows/iter (8 independent LDG.128 in flight) ----
        #pragma unroll
        for (int k = 0; k < 2; k++) {
            const int lr0 = wid * 4 + 2 * k;
            const int lr1 = lr0 + 1;
            const float4* p0 = a4 + (size_t)lr0 * F4;
            const float4* p1 = a4 + (size_t)lr1 * F4;

            float4 a[4], b[4];
            #pragma unroll
            for (int c = 0; c < 4; c++) {
                a[c] = __ldcs(&p0[c * 32 + lane]);
                b[c] = __ldcs(&p1[c * 32 + lane]);
            }
            #pragma unroll
            for (int c = 0; c < 4; c++) {
                unsigned n0 = (a[c].x != 0.0f ? 1u : 0u) | (a[c].y != 0.0f ? 2u : 0u) |
                              (a[c].z != 0.0f ? 4u : 0u) | (a[c].w != 0.0f ? 8u : 0u);
                unsigned n1 = (b[c].x != 0.0f ? 1u : 0u) | (b[c].y != 0.0f ? 2u : 0u) |
                              (b[c].z != 0.0f ? 4u : 0u) | (b[c].w != 0.0f ? 8u : 0u);
                unsigned w0 = n0 << (sub * 4);
                unsigned w1 = n1 << (sub * 4);
                w0 |= __shfl_xor_sync(0xffffffffu, w0, 1);
                w1 |= __shfl_xor_sync(0xffffffffu, w1, 1);
                w0 |= __shfl_xor_sync(0xffffffffu, w0, 2);
                w1 |= __shfl_xor_sync(0xffffffffu, w1, 2);
                w0 |= __shfl_xor_sync(0xffffffffu, w0, 4);
                w1 |= __shfl_xor_sync(0xffffffffu, w1, 4);
                if (sub == 0) {
                    s_bits[lr0 * WS + c * 4 + grp] = w0;
                    s_bits[lr1 * WS + c * 4 + grp] = w1;
                }
            }
        }
        __syncthreads();

        // ---- Patch own 32 rows: popc degree, fix diagonal, publish dis ----
        if (tid < RPC) {
            const int ig = r0 + tid;
            unsigned w[W];
            int cnt = 0;
            #pragma unroll
            for (int q = 0; q < W; q++) {
                w[q] = s_bits[tid * WS + q];
                cnt += __popc(w[q]);
            }
            const int dw = ig >> 5, db = ig & 31;
            const int diag = (w[dw] >> db) & 1;
            const int mask = (cnt != 0) ? 1 : 0;   // atom_mask
            const int deg  = cnt - diag + mask;    // degree_hat
            if (diag != mask) s_bits[tid * WS + dw] = w[dw] ^ (1u << db);
            g_dis[(size_t)batch * N + ig] = (deg > 0) ? rsqrtf((float)deg) : 0.0f;
        }
        __syncthreads();

        // ---- Publish + wait: all 16 chunks of this batch done ----
        if (tid == 0) {
            __threadfence();                       // dis stores visible gpu-wide
            atomicAdd(&g_done[batch], 1);
            volatile int* vf = &g_done[batch];
            while (*vf < CHUNKS) __nanosleep(32);
            __threadfence();                       // acquire
        }
        __syncthreads();

        // ---- Pull full dis vector (2 KB, L2-hot) ----
        if (tid < N / 4) {
            reinterpret_cast<float4*>(s_dis)[tid] =
                __ldcg(reinterpret_cast<const float4*>(g_dis + (size_t)batch * N) + tid);
        }
        __syncthreads();

        // ---- Phase B: out[i][j] = dis[i]*dis[j]*bit(i,j); STG.128 streaming ----
        const float4* d4 = reinterpret_cast<const float4*>(s_dis);
        float4 dreg[4];
        #pragma unroll
        for (int c = 0; c < 4; c++) dreg[c] = d4[c * 32 + lane];  // row-invariant

        float4* o4 = reinterpret_cast<float4*>(out) + ((size_t)batch * N + r0) * F4;

        #pragma unroll
        for (int k = 0; k < 2; k++) {
            const int lr0 = wid * 4 + 2 * k;
            const int lr1 = lr0 + 1;
            const float di0 = s_dis[r0 + lr0];
            const float di1 = s_dis[r0 + lr1];
            float4* q0 = o4 + (size_t)lr0 * F4;
            float4* q1 = o4 + (size_t)lr1 * F4;

            #pragma unroll
            for (int c = 0; c < 4; c++) {
                const unsigned w0 = s_bits[lr0 * WS + c * 4 + grp];  // broadcast
                const unsigned w1 = s_bits[lr1 * WS + c * 4 + grp];
                const unsigned n0 = (w0 >> (sub * 4)) & 0xFu;
                const unsigned n1 = (w1 >> (sub * 4)) & 0xFu;
                const float4 d = dreg[c];
                float4 v0, v1;
                v0.x = (n0 & 1u) ? di0 * d.x : 0.0f;
                v0.y = (n0 & 2u) ? di0 * d.y : 0.0f;
                v0.z = (n0 & 4u) ? di0 * d.z : 0.0f;
                v0.w = (n0 & 8u) ? di0 * d.w : 0.0f;
                v1.x = (n1 & 1u) ? di1 * d.x : 0.0f;
                v1.y = (n1 & 2u) ? di1 * d.y : 0.0f;
                v1.z = (n1 & 4u) ? di1 * d.z : 0.0f;
                v1.w = (n1 & 8u) ? di1 * d.w : 0.0f;
                __stcs(&q0[c * 32 + lane], v0);
                __stcs(&q1[c * 32 + lane], v1);
            }
        }
        __syncthreads();  // protect s_bits/s_dis before next ticket
    }
}

extern "C" void kernel_launch(void* const* d_in, const int* in_sizes, int n_in,
                              void* d_out, int out_size) {
    const float* adj = (const float*)d_in[0];
    float* out = (float*)d_out;
    (void)in_sizes; (void)n_in; (void)out_size;

    reset_kernel<<<1, B>>>();
    fused_normalize_kernel<<<GRID, THREADS>>>(adj, out);
}

// round 7
// speedup vs baseline: 1.7293x; 1.0189x over previous
#include <cuda_runtime.h>
#include <cstdint>

// B=256 batches of N=512 x 512 binary (0/1) float32 adjacency.
constexpr int B   = 256;
constexpr int N   = 512;
constexpr int W   = N / 32;    // 16 packed words per row
constexpr int WS  = W + 1;     // smem stride 17 -> conflict-free reads
constexpr int F4  = N / 4;     // 128 float4 per row
constexpr int RPC = 32;        // rows per CTA
constexpr int GRID = B * (N / RPC);  // 4096 CTAs, ~14+ waves -> ~99.6% slot util

// Scratch (__device__ globals: allocation-free rule).
// Slot layout (transposed): word (c*4+grp) of a row is stored at slot (grp*4+c),
// so the packing lane (sub==0 of group grp) can emit one uint4 = slots grp*4..+3.
__device__ unsigned g_bits[(size_t)B * N * W];  // 8 MB
__device__ float    g_dis [(size_t)B * N];      // 512 KB

// ---------------------------------------------------------------------------
// K1: pack + degree. 8 warps x 4 rows = 32 rows/CTA. 16 LDG.128 in flight/warp.
// ---------------------------------------------------------------------------
__global__ void __launch_bounds__(256)
pack_kernel(const float* __restrict__ adj) {
    const int bid   = blockIdx.x;
    const int batch = bid >> 4;
    const int r0    = (bid & 15) * RPC;

    const int tid  = threadIdx.x;
    const int wid  = tid >> 5;
    const int lane = tid & 31;
    const int sub  = lane & 7;
    const int grp  = lane >> 3;

    const int lr = wid * 4;                       // first of 4 rows for this warp
    const float4* a4 = reinterpret_cast<const float4*>(adj)
                     + ((size_t)batch * N + r0 + lr) * F4;

    // Front-batch all 16 independent 128-bit streaming loads.
    float4 v[4][4];
    #pragma unroll
    for (int r = 0; r < 4; r++)
        #pragma unroll
        for (int c = 0; c < 4; c++)
            v[r][c] = __ldcs(&a4[(size_t)r * F4 + c * 32 + lane]);

    #pragma unroll
    for (int r = 0; r < 4; r++) {
        unsigned wreg[4];
        int cnt = 0;
        #pragma unroll
        for (int c = 0; c < 4; c++) {
            unsigned nib = (v[r][c].x != 0.0f ? 1u : 0u) | (v[r][c].y != 0.0f ? 2u : 0u) |
                           (v[r][c].z != 0.0f ? 4u : 0u) | (v[r][c].w != 0.0f ? 8u : 0u);
            unsigned w = nib << (sub * 4);
            w |= __shfl_xor_sync(0xffffffffu, w, 1);
            w |= __shfl_xor_sync(0xffffffffu, w, 2);
            w |= __shfl_xor_sync(0xffffffffu, w, 4);   // all 8 lanes: word c*4+grp
            wreg[c] = w;
            cnt += __popc(w);                          // group-local popcount
        }
        // Sum the 4 group popcounts -> full row degree in every lane.
        cnt += __shfl_xor_sync(0xffffffffu, cnt, 8);
        cnt += __shfl_xor_sync(0xffffffffu, cnt, 16);

        const int ig = r0 + lr + r;                    // row index within batch
        const int dw = ig >> 5, db = ig & 31;
        const unsigned diagw = __shfl_sync(0xffffffffu, wreg[dw >> 2], (dw & 3) * 8);
        const int diag = (diagw >> db) & 1;
        const int mask = (cnt != 0) ? 1 : 0;           // atom_mask
        const int deg  = cnt - diag + mask;            // degree_hat
        if (grp == (dw & 3) && diag != mask) wreg[dw >> 2] ^= (1u << db);

        if (sub == 0) {                                // 4 lanes emit 64B/row
            uint4 pk = make_uint4(wreg[0], wreg[1], wreg[2], wreg[3]);
            reinterpret_cast<uint4*>(g_bits)[((size_t)batch * N + ig) * 4 + grp] = pk;
        }
        if (lane == 0)
            g_dis[(size_t)batch * N + ig] = (deg > 0) ? rsqrtf((float)deg) : 0.0f;
    }
}

// ---------------------------------------------------------------------------
// K2: out[i][j] = dis[i] * dis[j] * bit(i,j). 8 warps x 4 rows = 32 rows/CTA.
// ---------------------------------------------------------------------------
__global__ void __launch_bounds__(256)
scale_kernel(float* __restrict__ out) {
    __shared__ unsigned s_bits[RPC * WS];  // this CTA's 32 packed rows (slot order)
    __shared__ float    s_dis[N];          // full-batch d^-1/2

    const int bid   = blockIdx.x;
    const int batch = bid >> 4;
    const int r0    = (bid & 15) * RPC;

    const int tid  = threadIdx.x;
    const int wid  = tid >> 5;
    const int lane = tid & 31;
    const int sub  = lane & 7;
    const int grp  = lane >> 3;

    if (tid < 128) {
        // dis vector: 2 KB, L2-hot (16 CTAs per batch reuse it)
        reinterpret_cast<float4*>(s_dis)[tid] =
            __ldcg(reinterpret_cast<const float4*>(g_dis + (size_t)batch * N) + tid);
        // bits: 2 KB, slot order preserved
        const int row = tid >> 2, g = tid & 3;
        uint4 pk = __ldcg(reinterpret_cast<const uint4*>(g_bits)
                          + ((size_t)batch * N + r0 + row) * 4 + g);
        unsigned* dst = &s_bits[row * WS + g * 4];
        dst[0] = pk.x; dst[1] = pk.y; dst[2] = pk.z; dst[3] = pk.w;
    }
    __syncthreads();

    const float4* d4 = reinterpret_cast<const float4*>(s_dis);
    float4 dreg[4];
    #pragma unroll
    for (int c = 0; c < 4; c++) dreg[c] = d4[c * 32 + lane];  // row-invariant

    float4* o4 = reinterpret_cast<float4*>(out)
               + ((size_t)batch * N + r0 + wid * 4) * F4;

    #pragma unroll
    for (int r = 0; r < 4; r++) {
        const int lr = wid * 4 + r;
        const float di = s_dis[r0 + lr];
        float4* q = o4 + (size_t)r * F4;
        #pragma unroll
        for (int c = 0; c < 4; c++) {
            // word (c*4+grp) lives at slot (grp*4+c); 8-lane broadcast, no conflicts
            const unsigned w   = s_bits[lr * WS + grp * 4 + c];
            const unsigned nib = (w >> (sub * 4)) & 0xFu;
            const float4 d = dreg[c];
            float4 o;
            o.x = (nib & 1u) ? di * d.x : 0.0f;
            o.y = (nib & 2u) ? di * d.y : 0.0f;
            o.z = (nib & 4u) ? di * d.z : 0.0f;
            o.w = (nib & 8u) ? di * d.w : 0.0f;
            __stcs(&q[c * 32 + lane], o);  // coalesced STG.128 stream
        }
    }
}

extern "C" void kernel_launch(void* const* d_in, const int* in_sizes, int n_in,
                              void* d_out, int out_size) {
    const float* adj = (const float*)d_in[0];
    float* out = (float*)d_out;
    (void)in_sizes; (void)n_in; (void)out_size;

    pack_kernel<<<GRID, 256>>>(adj);
    scale_kernel<<<GRID, 256>>>(out);
}